// round 8
// baseline (speedup 1.0000x reference)
#include <cuda_runtime.h>
#include <cuda_bf16.h>

#define NQ      10
#define DIM     1024
#define LAYERS  8
#define THREADS 512
#define PAD_DIM (DIM + DIM / 16)

__device__ __forceinline__ int sp10(int x) {
    // suffix parity: bit p = XOR of bits p..9  (CNOT-chain permutation)
    x ^= x >> 1; x ^= x >> 2; x ^= x >> 4; x ^= x >> 8;
    return x;
}
__device__ __forceinline__ int padi(int j) { return j + (j >> 4); }

__device__ __forceinline__ float2 cfma2(float2 ca, float2 a, float2 cb, float2 b) {
    float2 r;
    r.x = ca.x*a.x - ca.y*a.y + cb.x*b.x - cb.y*b.y;
    r.y = ca.x*a.y + ca.y*a.x + cb.x*b.y + cb.y*b.x;
    return r;
}

__device__ __forceinline__ void gate_pair(float2& a0, float2& a1, const float2* m) {
    float2 n0 = cfma2(m[0], a0, m[1], a1);
    float2 n1 = cfma2(m[2], a0, m[3], a1);
    a0 = n0; a1 = n1;
}

__device__ __forceinline__ void gate_shfl2(float2& v0, float2& v1,
                                           int hibit, int mask, const float2* m) {
    const float2 ca = hibit ? m[3] : m[0];
    const float2 cb = hibit ? m[2] : m[1];
    float o0x = __shfl_xor_sync(0xffffffffu, v0.x, mask);
    float o0y = __shfl_xor_sync(0xffffffffu, v0.y, mask);
    float o1x = __shfl_xor_sync(0xffffffffu, v1.x, mask);
    float o1y = __shfl_xor_sync(0xffffffffu, v1.y, mask);
    v0 = cfma2(ca, v0, cb, make_float2(o0x, o0y));
    v1 = cfma2(ca, v1, cb, make_float2(o1x, o1y));
}

// outMode: 0 = real-part only (128,1024) f32; 1 = planar re-block then im-block
__global__ __launch_bounds__(THREADS)
void UnitaryR3Ansatz_kernel(const float* __restrict__ inp,
                            const float* __restrict__ params,
                            float* __restrict__ outF,
                            int outMode)
{
    const int b    = blockIdx.x;     // row 0..127
    const int copy = b >> 2;         // jnp.repeat(M, 4)
    const int t    = threadIdx.x;    // 0..511
    const int l    = t & 31;
    const int w    = t >> 5;         // 0..15

    __shared__ float2 mat[LAYERS][NQ][4];
    __shared__ float2 s0[PAD_DIM];
    __shared__ float2 s1[PAD_DIM];

    // --- all 80 rotation matrices (reference _r3 verbatim) ---
    if (t < LAYERS * NQ) {
        const int layer = t / NQ, q = t - layer * NQ;
        const float* a = params + ((size_t)(copy * LAYERS + layer) * NQ + q) * 3;
        const float omega = a[0], theta = a[1], phi = a[2];
        float s,  c;  sincosf(0.5f * theta,         &s,  &c);
        float sp, cp; sincosf(0.5f * (phi + omega), &sp, &cp);
        float sm, cm; sincosf(0.5f * (phi - omega), &sm, &cm);
        mat[layer][q][0] = make_float2( cp * c, -sp * c);   // m11
        mat[layer][q][1] = make_float2(-cm * s, -sm * s);   // m12
        mat[layer][q][2] = make_float2( cm * s, -sm * s);   // m21
        mat[layer][q][3] = make_float2( cp * c,  sp * c);   // m22
    }

    // --- layouts ---
    // A: j = [warp(4)=j9:6 | lane(5)=j5:1 | reg(1)=j0]
    // B: j = [reg(1)=j9 | lane(5)=j8:4 | warp(4)=j3:0]
    int aW[2], bI[2], eI[2];
    #pragma unroll
    for (int r = 0; r < 2; ++r) {
        const int jA = (w << 6) | (l << 1) | r;
        const int jB = (r << 9) | (l << 4) | w;
        aW[r] = padi(jA);
        bI[r] = padi(jB);
        eI[r] = padi(sp10(jA));
    }

    // --- load input (layout A, coalesced float2) ---
    const float2 in2 = *(const float2*)(inp + (size_t)b * DIM + ((w << 6) | (l << 1)));
    float2 v0 = make_float2(in2.x, 0.f);
    float2 v1 = make_float2(in2.y, 0.f);

    __syncthreads();   // matrices ready

    #pragma unroll
    for (int layer = 0; layer < LAYERS; ++layer) {
        const float2* M = &mat[layer][0][0];

        // ===== layout A: qubit 9 (reg), qubits 8..4 (lane bits 0..4) =====
        gate_pair(v0, v1, M + 9 * 4);
        #pragma unroll
        for (int p = 1; p <= 5; ++p) {
            const int mask = 1 << (p - 1);
            gate_shfl2(v0, v1, l & mask, mask, M + (9 - p) * 4);
        }

        // ===== A -> B remap (buffer s0) =====
        s0[aW[0]] = v0;
        s0[aW[1]] = v1;
        __syncthreads();
        v0 = s0[bI[0]];
        v1 = s0[bI[1]];

        // ===== layout B: qubit 0 (reg), qubits 1..3 (lane bits 4..2) =====
        gate_pair(v0, v1, M + 0 * 4);
        gate_shfl2(v0, v1, l & 16, 16, M + 1 * 4);
        gate_shfl2(v0, v1, l &  8,  8, M + 2 * 4);
        gate_shfl2(v0, v1, l &  4,  4, M + 3 * 4);

        // ===== B -> A remap composed with entangler (buffer s1) =====
        s1[bI[0]] = v0;
        s1[bI[1]] = v1;
        __syncthreads();
        v0 = s1[eI[0]];
        v1 = s1[eI[1]];
    }

    // --- output (layout A: v0,v1 are consecutive j = (w<<6)|(l<<1)+{0,1}) ---
    const size_t off = (size_t)b * DIM + ((w << 6) | (l << 1));
    *(float2*)(outF + off) = make_float2(v0.x, v1.x);
    if (outMode != 0) {
        *(float2*)(outF + (size_t)(128 * DIM) + off) = make_float2(v0.y, v1.y);
    }
}

extern "C" void kernel_launch(void* const* d_in, const int* in_sizes, int n_in,
                              void* d_out, int out_size)
{
    const float* inp    = (const float*)d_in[0];
    const float* params = (const float*)d_in[1];
    if (n_in >= 2 && in_sizes[0] < in_sizes[1]) {
        inp    = (const float*)d_in[1];
        params = (const float*)d_in[0];
    }
    const int outMode = (out_size == 128 * DIM) ? 0 : 1;

    UnitaryR3Ansatz_kernel<<<128, THREADS>>>(inp, params, (float*)d_out, outMode);
}